// round 15
// baseline (speedup 1.0000x reference)
#include <cuda_runtime.h>
#include <cuda_bf16.h>
#include <math.h>
#include <stdint.h>

// Problem constants
#define BATCH 4
#define TQ    128
#define DM    512
#define VOC   32000
#define ROWS  512          // BATCH*TQ
#define TK_Q  32
#define TK_H  512
#define TK_C  128
#define NTILE (VOC / 128)  // 250

// ---------------- scratch (device globals; no allocations allowed) ----------
__device__ float g_z[(size_t)ROWS * VOC];                 // 65.5 MB
__device__ float g_psum[(size_t)ROWS * NTILE];            // per-tile exp row sums
__device__ float g_S[ROWS];                               // logsumexp denominators
__device__ float g_C[ROWS];                               // log g3 - log S
__device__ __nv_bfloat16 g_vocab_bf[(size_t)VOC * DM];    // 32.7 MB
__device__ __nv_bfloat16 g_dt_bf[ROWS * DM];
__device__ __nv_bfloat16 g_eq_bf[BATCH * TK_Q * DM];
__device__ __nv_bfloat16 g_eh_bf[BATCH * TK_H * DM];
__device__ __nv_bfloat16 g_ec_bf[BATCH * TK_C * DM];
__device__ __nv_bfloat16 g_wbf[6 * DM * DM];              // Wqq,Wqh,Wqc,Wkq,Wkh,Wkc
__device__ __nv_bfloat16 g_qbf[3 * ROWS * DM];            // q projections (bf16)
__device__ __nv_bfloat16 g_kqbf[BATCH * TK_Q * DM];
__device__ __nv_bfloat16 g_khbf[BATCH * TK_H * DM];
__device__ __nv_bfloat16 g_kcbf[BATCH * TK_C * DM];
__device__ __nv_bfloat16 g_encqT[BATCH * DM * 64];        // enc^T, K padded 32->64
__device__ __nv_bfloat16 g_enchT[BATCH * DM * TK_H];
__device__ __nv_bfloat16 g_enccT[BATCH * DM * TK_C];
__device__ __nv_bfloat16 g_abq[ROWS * 64];                // bf16 attn (padded)
__device__ __nv_bfloat16 g_abh[ROWS * TK_H];
__device__ __nv_bfloat16 g_abc[ROWS * TK_C];
__device__ float g_aq[ROWS * TK_Q];                       // fp32 attn (scatter)
__device__ float g_ah[ROWS * TK_H];
__device__ float g_ac[ROWS * TK_C];
__device__ float g_vec[3 * ROWS * DM];
__device__ float g_gates[ROWS * 4];
__device__ int   g_tx64;

__device__ __forceinline__ int get_tx(const int* __restrict__ t, int k) {
    return g_tx64 ? t[2 * k] : t[k];
}

// ---------------- prep: text probe + fp32->bf16 convert + enc transpose -----
struct CvtJobs { const float* src[11]; __nv_bfloat16* dst[11]; };
#define CVT_TOTAL_F4 4898816
#define CVT_BLOCKS   19136          // ceil(CVT_TOTAL_F4 / 256)
#define TR_BLOCKS    1344           // 4 batches * 336 tiles
#define PREP_BLOCKS  (CVT_BLOCKS + TR_BLOCKS + 1)

__global__ __launch_bounds__(256) void prep_all(
    CvtJobs j,
    const float* __restrict__ encq, const float* __restrict__ ench,
    const float* __restrict__ encc,
    __nv_bfloat16* __restrict__ tq, __nv_bfloat16* __restrict__ th,
    __nv_bfloat16* __restrict__ tc,
    const int* __restrict__ txh)
{
    __shared__ float tile[32][33];
    const int blk = blockIdx.x;
    if (blk < CVT_BLOCKS) {
        const long sz[11] = {4096000, 65536, 16384, 262144, 65536,
                             65536, 65536, 65536, 65536, 65536, 65536};
        long i = (long)blk * 256 + threadIdx.x;
        if (i >= CVT_TOTAL_F4) return;
        long base = 0;
        const float* src = nullptr; __nv_bfloat16* dst = nullptr; long off = 0;
#pragma unroll
        for (int t = 0; t < 11; t++) {
            if (i >= base && i < base + sz[t]) { src = j.src[t]; dst = j.dst[t]; off = i - base; }
            base += sz[t];
        }
        float4 v = ((const float4*)src)[off];
        __nv_bfloat162* o = (__nv_bfloat162*)dst + off * 2;
        o[0] = __floats2bfloat162_rn(v.x, v.y);
        o[1] = __floats2bfloat162_rn(v.z, v.w);
    } else if (blk < CVT_BLOCKS + TR_BLOCKS) {
        int id = blk - CVT_BLOCKS;
        int b = id / 336, r = id % 336;
        const float* in; __nv_bfloat16* out; int ti, tj, ostride, isq = 0;
        if (r < 16)      { in = encq + (size_t)b * TK_Q * DM; out = tq + (size_t)b * DM * 64;
                           ti = 0; tj = r; ostride = 64; isq = 1; }
        else if (r < 272){ r -= 16; in = ench + (size_t)b * TK_H * DM; out = th + (size_t)b * DM * TK_H;
                           ti = r >> 4; tj = r & 15; ostride = TK_H; }
        else             { r -= 272; in = encc + (size_t)b * TK_C * DM; out = tc + (size_t)b * DM * TK_C;
                           ti = r >> 4; tj = r & 15; ostride = TK_C; }
        int k0 = ti * 32, d0 = tj * 32;
        int tx = threadIdx.x & 31, ty0 = threadIdx.x >> 5;
        for (int ty = ty0; ty < 32; ty += 8)
            tile[ty][tx] = in[(size_t)(k0 + ty) * DM + d0 + tx];
        __syncthreads();
        for (int ty = ty0; ty < 32; ty += 8) {
            out[(size_t)(d0 + ty) * ostride + k0 + tx] = __float2bfloat16(tile[tx][ty]);
            if (isq) out[(size_t)(d0 + ty) * ostride + 32 + tx] = __float2bfloat16(0.f);
        }
    } else {
        // text dtype probe: int64 iff all odd 32-bit words of 'his' row are 0.
        if (threadIdx.x < 32) {
            int nz = 0;
            for (int k = threadIdx.x; k < 512; k += 32)
                if (txh[2 * k + 1] != 0) nz = 1;
            unsigned m = __ballot_sync(0xffffffffu, nz);
            if (threadIdx.x == 0) g_tx64 = (m == 0u) ? 1 : 0;
        }
    }
}

// ---------------- mma.sync bf16 NT GEMM core (3-stage cp.async) -------------
#define SW128(x) ((x) ^ (((x) >> 3) & 0x70))
#define STAGE_BYTES 32768
#define MMA_SMEM (3 * STAGE_BYTES)

__device__ __forceinline__ uint32_t smem_u32(const void* p) {
    uint32_t a;
    asm("{ .reg .u64 t; cvta.to.shared.u64 t, %1; cvt.u32.u64 %0, t; }"
        : "=r"(a) : "l"(p));
    return a;
}
__device__ __forceinline__ void cp16(uint32_t d, const void* g) {
    asm volatile("cp.async.cg.shared.global [%0], [%1], 16;"
                 :: "r"(d), "l"(g));
}
__device__ __forceinline__ void cp16z(uint32_t d, const void* g, int sz) {
    asm volatile("cp.async.cg.shared.global [%0], [%1], 16, %2;"
                 :: "r"(d), "l"(g), "r"(sz));
}
__device__ __forceinline__ void cp_commit() {
    asm volatile("cp.async.commit_group;" ::: "memory");
}
__device__ __forceinline__ void cp_wait2() {
    asm volatile("cp.async.wait_group 2;" ::: "memory");
}
__device__ __forceinline__ void ldsm_x4(uint32_t& r0, uint32_t& r1,
                                        uint32_t& r2, uint32_t& r3, uint32_t a) {
    asm volatile("ldmatrix.sync.aligned.m8n8.x4.shared.b16 {%0,%1,%2,%3}, [%4];"
                 : "=r"(r0), "=r"(r1), "=r"(r2), "=r"(r3) : "r"(a));
}
__device__ __forceinline__ void mma16816(float* c, const uint32_t* a,
                                         const uint32_t* b) {
    asm volatile(
        "mma.sync.aligned.m16n8k16.row.col.f32.bf16.bf16.f32 "
        "{%0,%1,%2,%3},{%4,%5,%6,%7},{%8,%9},{%0,%1,%2,%3};"
        : "+f"(c[0]), "+f"(c[1]), "+f"(c[2]), "+f"(c[3])
        : "r"(a[0]), "r"(a[1]), "r"(a[2]), "r"(a[3]), "r"(b[0]), "r"(b[1]));
}

// Mainloop only: fills acc for a 128x128 tile at (m0, n0).
__device__ __forceinline__ void mma_mainloop(
    const __nv_bfloat16* __restrict__ A, const __nv_bfloat16* __restrict__ B,
    int N, int K, int m0, int n0, char* smem, float acc[4][4][4])
{
    const int tid = threadIdx.x, lane = tid & 31, wid = tid >> 5;
    const int wm = wid >> 2, wn = wid & 3;
    const uint32_t sbase = smem_u32(smem);
    const int NK = K >> 6;

#pragma unroll
    for (int i = 0; i < 4; i++)
#pragma unroll
        for (int jn = 0; jn < 4; jn++)
#pragma unroll
            for (int c = 0; c < 4; c++) acc[i][jn][c] = 0.f;

    const int lrow[4] = { (tid + 0) >> 3, (tid + 256) >> 3,
                          (tid + 512) >> 3, (tid + 768) >> 3 };
    const int lseg = tid & 7;

    auto issue = [&](int i) {
        uint32_t da = sbase + (uint32_t)(i % 3) * STAGE_BYTES;
#pragma unroll
        for (int j = 0; j < 4; j++) {
            int row = lrow[j];
            uint32_t soff = SW128(row * 128 + lseg * 16);
            cp16(da + soff, A + (size_t)(m0 + row) * K + i * 64 + lseg * 8);
            int bn = n0 + row;
            const __nv_bfloat16* gB =
                B + (size_t)(bn < N ? bn : 0) * K + i * 64 + lseg * 8;
            cp16z(da + 16384 + soff, gB, (bn < N) ? 16 : 0);
        }
    };

    issue(0); cp_commit();
    if (NK > 1) issue(1);
    cp_commit();

    for (int i = 0; i < NK; i++) {
        if (i + 2 < NK) issue(i + 2);
        cp_commit();
        cp_wait2();
        __syncthreads();
        const uint32_t sa = sbase + (uint32_t)(i % 3) * STAGE_BYTES;
        const uint32_t sb = sa + 16384;
#pragma unroll
        for (int k16 = 0; k16 < 4; k16++) {
            uint32_t af[4][4], bfr[2][4];
#pragma unroll
            for (int t = 0; t < 4; t++) {
                int row = wm * 64 + t * 16 + (lane & 15);
                int byt = k16 * 32 + (lane >> 4) * 16;
                ldsm_x4(af[t][0], af[t][1], af[t][2], af[t][3],
                        sa + SW128(row * 128 + byt));
            }
#pragma unroll
            for (int t = 0; t < 2; t++) {
                int nrow = wn * 32 + t * 16 + (lane & 7) + ((lane >> 4) << 3);
                int byt = k16 * 32 + ((lane >> 3) & 1) * 16;
                ldsm_x4(bfr[t][0], bfr[t][1], bfr[t][2], bfr[t][3],
                        sb + SW128(nrow * 128 + byt));
            }
#pragma unroll
            for (int mi = 0; mi < 4; mi++)
#pragma unroll
                for (int ni = 0; ni < 4; ni++)
                    mma16816(acc[mi][ni], af[mi], &bfr[ni >> 1][2 * (ni & 1)]);
        }
        __syncthreads();
    }
}

// Batched GEMMs via job table (incl. the big vocab GEMM with psum epilogue).
struct GemmJob {
    const __nv_bfloat16 *A, *B;
    const float* bias;
    void* C;
    float* psum;      // non-null -> fp32 out + per-tile exp row sums
    int N, K, outBf;
    int ntN, ntM;
    int colMajor;     // 1 -> tiles ordered n-major (CTAs sharing B adjacent)
    int tileEnd;
};
struct JobTable { GemmJob j[12]; int njobs; };

__global__ __launch_bounds__(256, 2) void mma_nt_jobs(JobTable jt) {
    extern __shared__ __align__(128) char smem[];
    int t = blockIdx.x, ji = 0, start = 0;
#pragma unroll
    for (int i = 0; i < 12; i++) {
        if (i < jt.njobs && t >= jt.j[i].tileEnd) { ji = i + 1; start = jt.j[i].tileEnd; }
    }
    const GemmJob& J = jt.j[ji];
    int local = t - start;
    int mt, nt;
    if (J.colMajor) { mt = local % J.ntM; nt = local / J.ntM; }
    else            { mt = local / J.ntN; nt = local % J.ntN; }
    int m0 = mt * 128, n0 = nt * 128;
    int N = J.N;
    const float* bias = J.bias;
    const int tid = threadIdx.x, lane = tid & 31, wid = tid >> 5;
    const int wm = wid >> 2, wn = wid & 3;

    float acc[4][4][4];
    mma_mainloop(J.A, J.B, N, J.K, m0, n0, smem, acc);

    if (J.psum) {
        float* C = (float*)J.C;
        float* rows = (float*)smem;      // reuse stage smem for 128x4 partials
#pragma unroll
        for (int mi = 0; mi < 4; mi++) {
            float s0 = 0.f, s1 = 0.f;
            int m = m0 + wm * 64 + mi * 16 + (lane >> 2);
#pragma unroll
            for (int ni = 0; ni < 4; ni++) {
                int n = n0 + wn * 32 + ni * 8 + (lane & 3) * 2;
                float c0 = acc[mi][ni][0], c1 = acc[mi][ni][1];
                float c2 = acc[mi][ni][2], c3 = acc[mi][ni][3];
                *(float2*)(C + (size_t)m * N + n) = make_float2(c0, c1);
                *(float2*)(C + (size_t)(m + 8) * N + n) = make_float2(c2, c3);
                s0 += __expf(c0) + __expf(c1);
                s1 += __expf(c2) + __expf(c3);
            }
            s0 += __shfl_xor_sync(0xffffffffu, s0, 1);
            s0 += __shfl_xor_sync(0xffffffffu, s0, 2);
            s1 += __shfl_xor_sync(0xffffffffu, s1, 1);
            s1 += __shfl_xor_sync(0xffffffffu, s1, 2);
            if ((lane & 3) == 0) {
                int lr = wm * 64 + mi * 16 + (lane >> 2);
                rows[lr * 4 + wn] = s0;
                rows[(lr + 8) * 4 + wn] = s1;
            }
        }
        __syncthreads();
        for (int idx = tid; idx < 128; idx += 256) {
            float s = rows[idx * 4] + rows[idx * 4 + 1]
                    + rows[idx * 4 + 2] + rows[idx * 4 + 3];
            J.psum[(size_t)(m0 + idx) * NTILE + nt] = s;
        }
    } else if (J.outBf) {
        __nv_bfloat16* C = (__nv_bfloat16*)J.C;
#pragma unroll
        for (int mi = 0; mi < 4; mi++)
#pragma unroll
            for (int ni = 0; ni < 4; ni++) {
                int n = n0 + wn * 32 + ni * 8 + (lane & 3) * 2;
                if (n >= N) continue;
                int m = m0 + wm * 64 + mi * 16 + (lane >> 2);
                float b0 = bias ? bias[n] : 0.f, b1 = bias ? bias[n + 1] : 0.f;
                *(__nv_bfloat162*)(C + (size_t)m * N + n) =
                    __floats2bfloat162_rn(acc[mi][ni][0] + b0, acc[mi][ni][1] + b1);
                *(__nv_bfloat162*)(C + (size_t)(m + 8) * N + n) =
                    __floats2bfloat162_rn(acc[mi][ni][2] + b0, acc[mi][ni][3] + b1);
            }
    } else {
        float* C = (float*)J.C;
#pragma unroll
        for (int mi = 0; mi < 4; mi++)
#pragma unroll
            for (int ni = 0; ni < 4; ni++) {
                int n = n0 + wn * 32 + ni * 8 + (lane & 3) * 2;
                if (n >= N) continue;
                int m = m0 + wm * 64 + mi * 16 + (lane >> 2);
                float b0 = bias ? bias[n] : 0.f, b1 = bias ? bias[n + 1] : 0.f;
                *(float2*)(C + (size_t)m * N + n) =
                    make_float2(acc[mi][ni][0] + b0, acc[mi][ni][1] + b1);
                *(float2*)(C + (size_t)(m + 8) * N + n) =
                    make_float2(acc[mi][ni][2] + b0, acc[mi][ni][3] + b1);
            }
    }
}

// ---------------- merged masked softmax (3 sources; fp32 + padded bf16 out) -
__global__ __launch_bounds__(128) void softmax_all(
    float* __restrict__ aq, float* __restrict__ ah, float* __restrict__ ac,
    __nv_bfloat16* __restrict__ abq, __nv_bfloat16* __restrict__ abh,
    __nv_bfloat16* __restrict__ abc,
    const int* __restrict__ txq, const int* __restrict__ txh,
    const int* __restrict__ txc)
{
    __shared__ float red[128];
    int gr = blockIdx.x;
    float* attn; const int* text; int Tk, Tkpad, r;
    __nv_bfloat16* abfb;
    if (gr < ROWS)          { attn = aq; text = txq; Tk = TK_Q; Tkpad = 64;
                              r = gr; abfb = abq; }
    else if (gr < 2 * ROWS) { attn = ah; text = txh; Tk = TK_H; Tkpad = TK_H;
                              r = gr - ROWS; abfb = abh; }
    else                    { attn = ac; text = txc; Tk = TK_C; Tkpad = TK_C;
                              r = gr - 2 * ROWS; abfb = abc; }
    const int b = r >> 7;
    float* row = attn + (long long)r * Tk;
    __nv_bfloat16* ab = abfb + (long long)r * Tkpad;
    const int* tb = text + (g_tx64 ? 2 : 1) * b * Tk;
    const int tid = threadIdx.x;
    const float scale = 0.04419417382415922f;   // 1/sqrt(512)

    float lmax = -3.4e38f;
    for (int k = tid; k < Tk; k += 128) {
        float s = row[k] * scale;
        if (get_tx(tb, k) == 0) s = -1e9f;
        row[k] = s;
        lmax = fmaxf(lmax, s);
    }
    red[tid] = lmax; __syncthreads();
    for (int s = 64; s > 0; s >>= 1) {
        if (tid < s) red[tid] = fmaxf(red[tid], red[tid + s]);
        __syncthreads();
    }
    const float mx = red[0];
    __syncthreads();
    float lsum = 0.f;
    for (int k = tid; k < Tk; k += 128) {
        float e = __expf(row[k] - mx);
        row[k] = e;
        lsum += e;
    }
    red[tid] = lsum; __syncthreads();
    for (int s = 64; s > 0; s >>= 1) {
        if (tid < s) red[tid] += red[tid + s];
        __syncthreads();
    }
    const float inv = 1.0f / red[0];
    for (int k = tid; k < Tk; k += 128) {
        float v = row[k] * inv;
        row[k] = v;
        ab[k] = __float2bfloat16(v);
    }
    for (int k = Tk + tid; k < Tkpad; k += 128)
        ab[k] = __float2bfloat16(0.f);
}

// ---------------- gates: S reduce + softmax(concat @ genW^T + genb) + C -----
__global__ __launch_bounds__(128) void gates_kernel(
    const float* __restrict__ dt, const float* __restrict__ tgt,
    const float* __restrict__ vec, const float* __restrict__ W,
    const float* __restrict__ bg, const float* __restrict__ psum,
    float* __restrict__ gates, float* __restrict__ Sout,
    float* __restrict__ Cout)
{
    __shared__ float red[4][128];
    __shared__ float sS;
    const int r = blockIdx.x, tid = threadIdx.x;

    // S = sum of this row's 250 per-tile exp sums
    float s = 0.f;
    for (int t = tid; t < NTILE; t += 128)
        s += psum[(size_t)r * NTILE + t];
    red[0][tid] = s; __syncthreads();
    for (int st = 64; st > 0; st >>= 1) {
        if (tid < st) red[0][tid] += red[0][tid + st];
        __syncthreads();
    }
    if (tid == 0) sS = red[0][0];
    __syncthreads();

    float a0 = 0, a1 = 0, a2 = 0, a3 = 0;
    for (int j = tid; j < 2560; j += 128) {
        const int part = j >> 9, d = j & 511;
        const float* src;
        switch (part) {
            case 0:  src = dt;                    break;
            case 1:  src = tgt;                   break;
            case 2:  src = vec;                   break;
            case 3:  src = vec + ROWS * DM;       break;
            default: src = vec + 2 * ROWS * DM;   break;
        }
        float x = src[(long long)r * DM + d];
        a0 = fmaf(W[j], x, a0);
        a1 = fmaf(W[2560 + j], x, a1);
        a2 = fmaf(W[5120 + j], x, a2);
        a3 = fmaf(W[7680 + j], x, a3);
    }
    red[0][tid] = a0; red[1][tid] = a1; red[2][tid] = a2; red[3][tid] = a3;
    __syncthreads();
    for (int st = 64; st > 0; st >>= 1) {
        if (tid < st) {
            red[0][tid] += red[0][tid + st]; red[1][tid] += red[1][tid + st];
            red[2][tid] += red[2][tid + st]; red[3][tid] += red[3][tid + st];
        }
        __syncthreads();
    }
    if (tid == 0) {
        float l0 = red[0][0] + bg[0], l1 = red[1][0] + bg[1];
        float l2 = red[2][0] + bg[2], l3 = red[3][0] + bg[3];
        float m = fmaxf(fmaxf(l0, l1), fmaxf(l2, l3));
        float e0 = expf(l0 - m), e1 = expf(l1 - m), e2 = expf(l2 - m), e3 = expf(l3 - m);
        float inv = 1.f / (e0 + e1 + e2 + e3);
        float g3 = e3 * inv;
        gates[r * 4 + 0] = e0 * inv; gates[r * 4 + 1] = e1 * inv;
        gates[r * 4 + 2] = e2 * inv; gates[r * 4 + 3] = g3;
        Sout[r] = sS;
        Cout[r] = logf(g3) - logf(sS);
    }
}

// ---------------- final2: scatter + single streaming output pass -------------
// Merges stream_out + fixup: per-row CTA builds the bf16 scatter buffer, then
// streams z once: untouched slots -> z + C; scattered -> log(gS*exp(z)+a).
__global__ __launch_bounds__(512) void final2_kernel(
    const float* __restrict__ z, const float* __restrict__ S_arr,
    const float* __restrict__ C_arr,
    const float* __restrict__ aq, const float* __restrict__ ah,
    const float* __restrict__ ac,
    const int* __restrict__ tq, const int* __restrict__ th,
    const int* __restrict__ tc,
    const float* __restrict__ gates, float* __restrict__ out)
{
    extern __shared__ __nv_bfloat162 addb[];   // VOC/2 pairs (64 KB)
    const int r = blockIdx.x, b = r >> 7, tid = threadIdx.x;
    const int w = g_tx64 ? 2 : 1;

    uint4* zb = (uint4*)addb;
    for (int v = tid; v < VOC * 2 / 16; v += 512) zb[v] = make_uint4(0u, 0u, 0u, 0u);
    const float g0 = gates[r * 4 + 0], g1 = gates[r * 4 + 1];
    const float g2 = gates[r * 4 + 2], g3 = gates[r * 4 + 3];
    __syncthreads();

    auto scat = [&](int idx, float v) {
        __nv_bfloat16 bv = __float2bfloat16(v);
        __nv_bfloat16 bz = __float2bfloat16(0.f);
        __nv_bfloat162 p;
        if (idx & 1) { p.x = bz; p.y = bv; } else { p.x = bv; p.y = bz; }
        atomicAdd(&addb[idx >> 1], p);
    };
    const int* tqb = tq + w * b * TK_Q;
    const int* thb = th + w * b * TK_H;
    const int* tcb = tc + w * b * TK_C;
    if (tid < TK_Q)
        scat(get_tx(tqb, tid), g0 * aq[(long long)r * TK_Q + tid]);
    for (int k = tid; k < TK_H; k += 512)
        scat(get_tx(thb, k), g1 * ah[(long long)r * TK_H + k]);
    if (tid < TK_C)
        scat(get_tx(tcb, tid), g2 * ac[(long long)r * TK_C + tid]);
    __syncthreads();

    const float S = S_arr[r];
    const float C = C_arr[r];
    const float gS = g3 / S;

    const float4* zr4 = (const float4*)(z + (long long)r * VOC);
    float4* orow = (float4*)(out + (long long)r * VOC);
    for (int i = tid; i < VOC / 4; i += 512) {
        float4 zz = __ldcs(zr4 + i);
        __nv_bfloat162 p0 = addb[i * 2], p1 = addb[i * 2 + 1];
        float a0 = __bfloat162float(p0.x), a1 = __bfloat162float(p0.y);
        float a2 = __bfloat162float(p1.x), a3 = __bfloat162float(p1.y);
        float4 o;
        o.x = (a0 == 0.f) ? zz.x + C : logf(fmaf(gS, __expf(zz.x), a0));
        o.y = (a1 == 0.f) ? zz.y + C : logf(fmaf(gS, __expf(zz.y), a1));
        o.z = (a2 == 0.f) ? zz.z + C : logf(fmaf(gS, __expf(zz.z), a2));
        o.w = (a3 == 0.f) ? zz.w + C : logf(fmaf(gS, __expf(zz.w), a3));
        __stcs(orow + i, o);
    }
}

// ---------------- launch ----------------------------------------------------
extern "C" void kernel_launch(void* const* d_in, const int* in_sizes, int n_in,
                              void* d_out, int out_size)
{
    const float* dt   = (const float*)d_in[0];
    const float* tgt  = (const float*)d_in[1];
    const float* encq = (const float*)d_in[2];
    const float* ench = (const float*)d_in[3];
    const float* encc = (const float*)d_in[4];
    const int*   txq  = (const int*)d_in[5];
    const int*   txh  = (const int*)d_in[6];
    const int*   txc  = (const int*)d_in[7];
    const float* vocab = (const float*)d_in[11];
    const float* Wqq = (const float*)d_in[12]; const float* bqq = (const float*)d_in[13];
    const float* Wkq = (const float*)d_in[14]; const float* bkq = (const float*)d_in[15];
    const float* Wqh = (const float*)d_in[16]; const float* bqh = (const float*)d_in[17];
    const float* Wkh = (const float*)d_in[18]; const float* bkh = (const float*)d_in[19];
    const float* Wqc = (const float*)d_in[20]; const float* bqc = (const float*)d_in[21];
    const float* Wkc = (const float*)d_in[22]; const float* bkc = (const float*)d_in[23];
    const float* genW = (const float*)d_in[24]; const float* genb = (const float*)d_in[25];
    float* out = (float*)d_out;

    float *zP, *psP, *SP, *CP, *aqP, *ahP, *acP, *vP, *gP;
    __nv_bfloat16 *vbP, *dbP, *eqP, *ehP, *ecP, *wbP, *qbP, *kqP, *khP, *kcP;
    __nv_bfloat16 *tqTP, *thTP, *tcTP, *abqP, *abhP, *abcP;
    cudaGetSymbolAddress((void**)&zP,  g_z);
    cudaGetSymbolAddress((void**)&psP, g_psum);
    cudaGetSymbolAddress((void**)&SP,  g_S);
    cudaGetSymbolAddress((void**)&CP,  g_C);
    cudaGetSymbolAddress((void**)&vbP, g_vocab_bf);
    cudaGetSymbolAddress((void**)&dbP, g_dt_bf);
    cudaGetSymbolAddress((void**)&eqP, g_eq_bf);
    cudaGetSymbolAddress((void**)&ehP, g_eh_bf);
    cudaGetSymbolAddress((void**)&ecP, g_ec_bf);
    cudaGetSymbolAddress((void**)&wbP, g_wbf);
    cudaGetSymbolAddress((void**)&qbP, g_qbf);
    cudaGetSymbolAddress((void**)&kqP, g_kqbf);
    cudaGetSymbolAddress((void**)&khP, g_khbf);
    cudaGetSymbolAddress((void**)&kcP, g_kcbf);
    cudaGetSymbolAddress((void**)&tqTP, g_encqT);
    cudaGetSymbolAddress((void**)&thTP, g_enchT);
    cudaGetSymbolAddress((void**)&tcTP, g_enccT);
    cudaGetSymbolAddress((void**)&abqP, g_abq);
    cudaGetSymbolAddress((void**)&abhP, g_abh);
    cudaGetSymbolAddress((void**)&abcP, g_abc);
    cudaGetSymbolAddress((void**)&aqP, g_aq);
    cudaGetSymbolAddress((void**)&ahP, g_ah);
    cudaGetSymbolAddress((void**)&acP, g_ac);
    cudaGetSymbolAddress((void**)&vP,  g_vec);
    cudaGetSymbolAddress((void**)&gP,  g_gates);

    cudaFuncSetAttribute(final2_kernel,
                         cudaFuncAttributeMaxDynamicSharedMemorySize, VOC * 2);
    cudaFuncSetAttribute(mma_nt_jobs,
                         cudaFuncAttributeMaxDynamicSharedMemorySize, MMA_SMEM);

    // Prep: probe + fp32->bf16 conversions + enc^T, one launch.
    CvtJobs cj;
    cj.src[0] = vocab; cj.dst[0] = vbP;
    cj.src[1] = dt;    cj.dst[1] = dbP;
    cj.src[2] = encq;  cj.dst[2] = eqP;
    cj.src[3] = ench;  cj.dst[3] = ehP;
    cj.src[4] = encc;  cj.dst[4] = ecP;
    cj.src[5] = Wqq;   cj.dst[5] = wbP + 0 * DM * DM;
    cj.src[6] = Wqh;   cj.dst[6] = wbP + 1 * DM * DM;
    cj.src[7] = Wqc;   cj.dst[7] = wbP + 2 * DM * DM;
    cj.src[8] = Wkq;   cj.dst[8] = wbP + 3 * DM * DM;
    cj.src[9] = Wkh;   cj.dst[9] = wbP + 4 * DM * DM;
    cj.src[10] = Wkc;  cj.dst[10] = wbP + 5 * DM * DM;
    prep_all<<<PREP_BLOCKS, 256>>>(cj, encq, ench, encc, tqTP, thTP, tcTP, txh);

    // Mega launch: 6 projections (first, critical path) + big vocab GEMM.
    {
        JobTable jt{}; int cum = 0; int i = 0;
        auto addproj = [&](const __nv_bfloat16* A, const __nv_bfloat16* B,
                           const float* bias, void* C, int M) {
            jt.j[i].A = A; jt.j[i].B = B; jt.j[i].bias = bias; jt.j[i].C = C;
            jt.j[i].psum = nullptr;
            jt.j[i].N = DM; jt.j[i].K = DM; jt.j[i].outBf = 1;
            jt.j[i].ntN = DM / 128; jt.j[i].ntM = M / 128; jt.j[i].colMajor = 0;
            cum += (M / 128) * (DM / 128);
            jt.j[i].tileEnd = cum;
            i++;
        };
        addproj(dbP, wbP + 0 * DM * DM, bqq, qbP + 0 * ROWS * DM, ROWS);
        addproj(dbP, wbP + 1 * DM * DM, bqh, qbP + 1 * ROWS * DM, ROWS);
        addproj(dbP, wbP + 2 * DM * DM, bqc, qbP + 2 * ROWS * DM, ROWS);
        addproj(eqP, wbP + 3 * DM * DM, bkq, kqP, BATCH * TK_Q);
        addproj(ehP, wbP + 4 * DM * DM, bkh, khP, BATCH * TK_H);
        addproj(ecP, wbP + 5 * DM * DM, bkc, kcP, BATCH * TK_C);
        // big vocab GEMM, column-major tile order for B L2 reuse
        jt.j[i].A = dbP; jt.j[i].B = vbP; jt.j[i].bias = nullptr; jt.j[i].C = zP;
        jt.j[i].psum = psP;
        jt.j[i].N = VOC; jt.j[i].K = DM; jt.j[i].outBf = 0;
        jt.j[i].ntN = NTILE; jt.j[i].ntM = ROWS / 128; jt.j[i].colMajor = 1;
        cum += NTILE * (ROWS / 128);
        jt.j[i].tileEnd = cum;
        i++;
        jt.njobs = i;
        mma_nt_jobs<<<cum, 256, MMA_SMEM>>>(jt);
    }

    // Scores: all 12 score GEMMs in one launch (24 tiles)
    {
        JobTable jt{}; int cum = 0, i = 0;
        auto addscore = [&](const __nv_bfloat16* A, const __nv_bfloat16* B,
                            float* C, int N) {
            jt.j[i].A = A; jt.j[i].B = B; jt.j[i].bias = nullptr; jt.j[i].C = C;
            jt.j[i].psum = nullptr;
            jt.j[i].N = N; jt.j[i].K = DM; jt.j[i].outBf = 0;
            int ntN = (N + 127) / 128;
            jt.j[i].ntN = ntN; jt.j[i].ntM = 1; jt.j[i].colMajor = 0;
            cum += ntN;
            jt.j[i].tileEnd = cum;
            i++;
        };
        for (int b = 0; b < BATCH; b++)
            addscore(qbP + 0 * ROWS * DM + b * TQ * DM, kqP + b * TK_Q * DM,
                     aqP + b * TQ * TK_Q, TK_Q);
        for (int b = 0; b < BATCH; b++)
            addscore(qbP + 1 * ROWS * DM + b * TQ * DM, khP + b * TK_H * DM,
                     ahP + b * TQ * TK_H, TK_H);
        for (int b = 0; b < BATCH; b++)
            addscore(qbP + 2 * ROWS * DM + b * TQ * DM, kcP + b * TK_C * DM,
                     acP + b * TQ * TK_C, TK_C);
        jt.njobs = 12;
        mma_nt_jobs<<<cum, 256, MMA_SMEM>>>(jt);
    }

    // Masked softmax (merged; emits fp32 + padded bf16 attn)
    softmax_all<<<3 * ROWS, 128>>>(aqP, ahP, acP, abqP, abhP, abcP,
                                   txq, txh, txc);

    // Vec: all 12 vec GEMMs on tensor cores (48 tiles): vec = attn @ enc
    {
        JobTable jt{}; int cum = 0, i = 0;
        auto addvec = [&](const __nv_bfloat16* A, const __nv_bfloat16* B,
                          float* C, int K) {
            jt.j[i].A = A; jt.j[i].B = B; jt.j[i].bias = nullptr; jt.j[i].C = C;
            jt.j[i].psum = nullptr;
            jt.j[i].N = DM; jt.j[i].K = K; jt.j[i].outBf = 0;
            jt.j[i].ntN = DM / 128; jt.j[i].ntM = 1; jt.j[i].colMajor = 0;
            cum += DM / 128;
            jt.j[i].tileEnd = cum;
            i++;
        };
        for (int b = 0; b < BATCH; b++)
            addvec(abqP + b * TQ * 64, tqTP + b * DM * 64,
                   vP + 0 * ROWS * DM + b * TQ * DM, 64);
        for (int b = 0; b < BATCH; b++)
            addvec(abhP + b * TQ * TK_H, thTP + b * DM * TK_H,
                   vP + 1 * ROWS * DM + b * TQ * DM, TK_H);
        for (int b = 0; b < BATCH; b++)
            addvec(abcP + b * TQ * TK_C, tcTP + b * DM * TK_C,
                   vP + 2 * ROWS * DM + b * TQ * DM, TK_C);
        jt.njobs = 12;
        mma_nt_jobs<<<cum, 256, MMA_SMEM>>>(jt);
    }

    // Gates (+ S reduction + C = log g3 - log S)
    gates_kernel<<<ROWS, 128>>>(dt, tgt, vP, genW, genb, psP, gP, SP, CP);

    // Final: scatter + single streaming pass (merged stream_out + fixup)
    final2_kernel<<<ROWS, 512, VOC * 2>>>(zP, SP, CP, aqP, ahP, acP,
                                          txq, txh, txc, gP, out);
}

// round 16
// speedup vs baseline: 1.4916x; 1.4916x over previous
#include <cuda_runtime.h>
#include <cuda_bf16.h>
#include <math.h>
#include <stdint.h>

// Problem constants
#define BATCH 4
#define TQ    128
#define DM    512
#define VOC   32000
#define ROWS  512          // BATCH*TQ
#define TK_Q  32
#define TK_H  512
#define TK_C  128
#define NTILE (VOC / 128)  // 250

// ---------------- scratch (device globals; no allocations allowed) ----------
__device__ float g_z[(size_t)ROWS * VOC];                 // 65.5 MB
__device__ float g_psum[(size_t)ROWS * NTILE];            // per-tile exp row sums
__device__ float g_S[ROWS];                               // logsumexp denominators
__device__ float g_C[ROWS];                               // log g3 - log S
__device__ __nv_bfloat16 g_vocab_bf[(size_t)VOC * DM];    // 32.7 MB
__device__ __nv_bfloat16 g_dt_bf[ROWS * DM];
__device__ __nv_bfloat16 g_eq_bf[BATCH * TK_Q * DM];
__device__ __nv_bfloat16 g_eh_bf[BATCH * TK_H * DM];
__device__ __nv_bfloat16 g_ec_bf[BATCH * TK_C * DM];
__device__ __nv_bfloat16 g_wbf[6 * DM * DM];              // Wqq,Wqh,Wqc,Wkq,Wkh,Wkc
__device__ __nv_bfloat16 g_qbf[3 * ROWS * DM];            // q projections (bf16)
__device__ __nv_bfloat16 g_kqbf[BATCH * TK_Q * DM];
__device__ __nv_bfloat16 g_khbf[BATCH * TK_H * DM];
__device__ __nv_bfloat16 g_kcbf[BATCH * TK_C * DM];
__device__ __nv_bfloat16 g_encqT[BATCH * DM * 64];        // enc^T, K padded 32->64
__device__ __nv_bfloat16 g_enchT[BATCH * DM * TK_H];
__device__ __nv_bfloat16 g_enccT[BATCH * DM * TK_C];
__device__ __nv_bfloat16 g_abq[ROWS * 64];                // bf16 attn (padded)
__device__ __nv_bfloat16 g_abh[ROWS * TK_H];
__device__ __nv_bfloat16 g_abc[ROWS * TK_C];
__device__ float g_aq[ROWS * TK_Q];                       // fp32 attn (scatter)
__device__ float g_ah[ROWS * TK_H];
__device__ float g_ac[ROWS * TK_C];
__device__ float g_vec[3 * ROWS * DM];
__device__ float g_gates[ROWS * 4];
__device__ int   g_tx64;

__device__ __forceinline__ int get_tx(const int* __restrict__ t, int k) {
    return g_tx64 ? t[2 * k] : t[k];
}

// ---------------- prep: text probe + fp32->bf16 convert + enc transpose -----
struct CvtJobs { const float* src[11]; __nv_bfloat16* dst[11]; };
#define CVT_TOTAL_F4 4898816
#define CVT_BLOCKS   19136          // ceil(CVT_TOTAL_F4 / 256)
#define TR_BLOCKS    1344           // 4 batches * 336 tiles
#define PREP_BLOCKS  (CVT_BLOCKS + TR_BLOCKS + 1)

__global__ __launch_bounds__(256) void prep_all(
    CvtJobs j,
    const float* __restrict__ encq, const float* __restrict__ ench,
    const float* __restrict__ encc,
    __nv_bfloat16* __restrict__ tq, __nv_bfloat16* __restrict__ th,
    __nv_bfloat16* __restrict__ tc,
    const int* __restrict__ txh)
{
    __shared__ float tile[32][33];
    const int blk = blockIdx.x;
    if (blk < CVT_BLOCKS) {
        const long sz[11] = {4096000, 65536, 16384, 262144, 65536,
                             65536, 65536, 65536, 65536, 65536, 65536};
        long i = (long)blk * 256 + threadIdx.x;
        if (i >= CVT_TOTAL_F4) return;
        long base = 0;
        const float* src = nullptr; __nv_bfloat16* dst = nullptr; long off = 0;
#pragma unroll
        for (int t = 0; t < 11; t++) {
            if (i >= base && i < base + sz[t]) { src = j.src[t]; dst = j.dst[t]; off = i - base; }
            base += sz[t];
        }
        float4 v = ((const float4*)src)[off];
        __nv_bfloat162* o = (__nv_bfloat162*)dst + off * 2;
        o[0] = __floats2bfloat162_rn(v.x, v.y);
        o[1] = __floats2bfloat162_rn(v.z, v.w);
    } else if (blk < CVT_BLOCKS + TR_BLOCKS) {
        int id = blk - CVT_BLOCKS;
        int b = id / 336, r = id % 336;
        const float* in; __nv_bfloat16* out; int ti, tj, ostride, isq = 0;
        if (r < 16)      { in = encq + (size_t)b * TK_Q * DM; out = tq + (size_t)b * DM * 64;
                           ti = 0; tj = r; ostride = 64; isq = 1; }
        else if (r < 272){ r -= 16; in = ench + (size_t)b * TK_H * DM; out = th + (size_t)b * DM * TK_H;
                           ti = r >> 4; tj = r & 15; ostride = TK_H; }
        else             { r -= 272; in = encc + (size_t)b * TK_C * DM; out = tc + (size_t)b * DM * TK_C;
                           ti = r >> 4; tj = r & 15; ostride = TK_C; }
        int k0 = ti * 32, d0 = tj * 32;
        int tx = threadIdx.x & 31, ty0 = threadIdx.x >> 5;
        for (int ty = ty0; ty < 32; ty += 8)
            tile[ty][tx] = in[(size_t)(k0 + ty) * DM + d0 + tx];
        __syncthreads();
        for (int ty = ty0; ty < 32; ty += 8) {
            out[(size_t)(d0 + ty) * ostride + k0 + tx] = __float2bfloat16(tile[tx][ty]);
            if (isq) out[(size_t)(d0 + ty) * ostride + 32 + tx] = __float2bfloat16(0.f);
        }
    } else {
        // text dtype probe: int64 iff all odd 32-bit words of 'his' row are 0.
        if (threadIdx.x < 32) {
            int nz = 0;
            for (int k = threadIdx.x; k < 512; k += 32)
                if (txh[2 * k + 1] != 0) nz = 1;
            unsigned m = __ballot_sync(0xffffffffu, nz);
            if (threadIdx.x == 0) g_tx64 = (m == 0u) ? 1 : 0;
        }
    }
}

// ---------------- mma.sync bf16 NT GEMM core (3-stage cp.async) -------------
#define SW128(x) ((x) ^ (((x) >> 3) & 0x70))
#define STAGE_BYTES 32768
#define MMA_SMEM (3 * STAGE_BYTES)

__device__ __forceinline__ uint32_t smem_u32(const void* p) {
    uint32_t a;
    asm("{ .reg .u64 t; cvta.to.shared.u64 t, %1; cvt.u32.u64 %0, t; }"
        : "=r"(a) : "l"(p));
    return a;
}
__device__ __forceinline__ void cp16(uint32_t d, const void* g) {
    asm volatile("cp.async.cg.shared.global [%0], [%1], 16;"
                 :: "r"(d), "l"(g));
}
__device__ __forceinline__ void cp16z(uint32_t d, const void* g, int sz) {
    asm volatile("cp.async.cg.shared.global [%0], [%1], 16, %2;"
                 :: "r"(d), "l"(g), "r"(sz));
}
__device__ __forceinline__ void cp_commit() {
    asm volatile("cp.async.commit_group;" ::: "memory");
}
__device__ __forceinline__ void cp_wait2() {
    asm volatile("cp.async.wait_group 2;" ::: "memory");
}
__device__ __forceinline__ void ldsm_x4(uint32_t& r0, uint32_t& r1,
                                        uint32_t& r2, uint32_t& r3, uint32_t a) {
    asm volatile("ldmatrix.sync.aligned.m8n8.x4.shared.b16 {%0,%1,%2,%3}, [%4];"
                 : "=r"(r0), "=r"(r1), "=r"(r2), "=r"(r3) : "r"(a));
}
__device__ __forceinline__ void mma16816(float* c, const uint32_t* a,
                                         const uint32_t* b) {
    asm volatile(
        "mma.sync.aligned.m16n8k16.row.col.f32.bf16.bf16.f32 "
        "{%0,%1,%2,%3},{%4,%5,%6,%7},{%8,%9},{%0,%1,%2,%3};"
        : "+f"(c[0]), "+f"(c[1]), "+f"(c[2]), "+f"(c[3])
        : "r"(a[0]), "r"(a[1]), "r"(a[2]), "r"(a[3]), "r"(b[0]), "r"(b[1]));
}

// Mainloop only: fills acc for a 128x128 tile at (m0, n0).
__device__ __forceinline__ void mma_mainloop(
    const __nv_bfloat16* __restrict__ A, const __nv_bfloat16* __restrict__ B,
    int N, int K, int m0, int n0, char* smem, float acc[4][4][4])
{
    const int tid = threadIdx.x, lane = tid & 31, wid = tid >> 5;
    const int wm = wid >> 2, wn = wid & 3;
    const uint32_t sbase = smem_u32(smem);
    const int NK = K >> 6;

#pragma unroll
    for (int i = 0; i < 4; i++)
#pragma unroll
        for (int jn = 0; jn < 4; jn++)
#pragma unroll
            for (int c = 0; c < 4; c++) acc[i][jn][c] = 0.f;

    const int lrow[4] = { (tid + 0) >> 3, (tid + 256) >> 3,
                          (tid + 512) >> 3, (tid + 768) >> 3 };
    const int lseg = tid & 7;

    auto issue = [&](int i) {
        uint32_t da = sbase + (uint32_t)(i % 3) * STAGE_BYTES;
#pragma unroll
        for (int j = 0; j < 4; j++) {
            int row = lrow[j];
            uint32_t soff = SW128(row * 128 + lseg * 16);
            cp16(da + soff, A + (size_t)(m0 + row) * K + i * 64 + lseg * 8);
            int bn = n0 + row;
            const __nv_bfloat16* gB =
                B + (size_t)(bn < N ? bn : 0) * K + i * 64 + lseg * 8;
            cp16z(da + 16384 + soff, gB, (bn < N) ? 16 : 0);
        }
    };

    issue(0); cp_commit();
    if (NK > 1) issue(1);
    cp_commit();

    for (int i = 0; i < NK; i++) {
        if (i + 2 < NK) issue(i + 2);
        cp_commit();
        cp_wait2();
        __syncthreads();
        const uint32_t sa = sbase + (uint32_t)(i % 3) * STAGE_BYTES;
        const uint32_t sb = sa + 16384;
#pragma unroll
        for (int k16 = 0; k16 < 4; k16++) {
            uint32_t af[4][4], bfr[2][4];
#pragma unroll
            for (int t = 0; t < 4; t++) {
                int row = wm * 64 + t * 16 + (lane & 15);
                int byt = k16 * 32 + (lane >> 4) * 16;
                ldsm_x4(af[t][0], af[t][1], af[t][2], af[t][3],
                        sa + SW128(row * 128 + byt));
            }
#pragma unroll
            for (int t = 0; t < 2; t++) {
                int nrow = wn * 32 + t * 16 + (lane & 7) + ((lane >> 4) << 3);
                int byt = k16 * 32 + ((lane >> 3) & 1) * 16;
                ldsm_x4(bfr[t][0], bfr[t][1], bfr[t][2], bfr[t][3],
                        sb + SW128(nrow * 128 + byt));
            }
#pragma unroll
            for (int mi = 0; mi < 4; mi++)
#pragma unroll
                for (int ni = 0; ni < 4; ni++)
                    mma16816(acc[mi][ni], af[mi], &bfr[ni >> 1][2 * (ni & 1)]);
        }
        __syncthreads();
    }
}

// Batched GEMMs via job table (incl. the big vocab GEMM with psum epilogue).
struct GemmJob {
    const __nv_bfloat16 *A, *B;
    const float* bias;
    void* C;
    float* psum;      // non-null -> fp32 out + per-tile exp row sums
    int N, K, outBf;
    int ntN, ntM;
    int colMajor;     // 1 -> tiles ordered n-major (CTAs sharing B adjacent)
    int tileEnd;
};
struct JobTable { GemmJob j[12]; int njobs; };

__global__ __launch_bounds__(256, 2) void mma_nt_jobs(JobTable jt) {
    extern __shared__ __align__(128) char smem[];
    int t = blockIdx.x, ji = 0, start = 0;
#pragma unroll
    for (int i = 0; i < 12; i++) {
        if (i < jt.njobs && t >= jt.j[i].tileEnd) { ji = i + 1; start = jt.j[i].tileEnd; }
    }
    const GemmJob& J = jt.j[ji];
    int local = t - start;
    int mt, nt;
    if (J.colMajor) { mt = local % J.ntM; nt = local / J.ntM; }
    else            { mt = local / J.ntN; nt = local % J.ntN; }
    int m0 = mt * 128, n0 = nt * 128;
    int N = J.N;
    const float* bias = J.bias;
    const int tid = threadIdx.x, lane = tid & 31, wid = tid >> 5;
    const int wm = wid >> 2, wn = wid & 3;

    float acc[4][4][4];
    mma_mainloop(J.A, J.B, N, J.K, m0, n0, smem, acc);

    if (J.psum) {
        float* C = (float*)J.C;
        float* rows = (float*)smem;      // reuse stage smem for 128x4 partials
#pragma unroll
        for (int mi = 0; mi < 4; mi++) {
            float s0 = 0.f, s1 = 0.f;
            int m = m0 + wm * 64 + mi * 16 + (lane >> 2);
#pragma unroll
            for (int ni = 0; ni < 4; ni++) {
                int n = n0 + wn * 32 + ni * 8 + (lane & 3) * 2;
                float c0 = acc[mi][ni][0], c1 = acc[mi][ni][1];
                float c2 = acc[mi][ni][2], c3 = acc[mi][ni][3];
                *(float2*)(C + (size_t)m * N + n) = make_float2(c0, c1);
                *(float2*)(C + (size_t)(m + 8) * N + n) = make_float2(c2, c3);
                s0 += __expf(c0) + __expf(c1);
                s1 += __expf(c2) + __expf(c3);
            }
            s0 += __shfl_xor_sync(0xffffffffu, s0, 1);
            s0 += __shfl_xor_sync(0xffffffffu, s0, 2);
            s1 += __shfl_xor_sync(0xffffffffu, s1, 1);
            s1 += __shfl_xor_sync(0xffffffffu, s1, 2);
            if ((lane & 3) == 0) {
                int lr = wm * 64 + mi * 16 + (lane >> 2);
                rows[lr * 4 + wn] = s0;
                rows[(lr + 8) * 4 + wn] = s1;
            }
        }
        __syncthreads();
        for (int idx = tid; idx < 128; idx += 256) {
            float s = rows[idx * 4] + rows[idx * 4 + 1]
                    + rows[idx * 4 + 2] + rows[idx * 4 + 3];
            J.psum[(size_t)(m0 + idx) * NTILE + nt] = s;
        }
    } else if (J.outBf) {
        __nv_bfloat16* C = (__nv_bfloat16*)J.C;
#pragma unroll
        for (int mi = 0; mi < 4; mi++)
#pragma unroll
            for (int ni = 0; ni < 4; ni++) {
                int n = n0 + wn * 32 + ni * 8 + (lane & 3) * 2;
                if (n >= N) continue;
                int m = m0 + wm * 64 + mi * 16 + (lane >> 2);
                float b0 = bias ? bias[n] : 0.f, b1 = bias ? bias[n + 1] : 0.f;
                *(__nv_bfloat162*)(C + (size_t)m * N + n) =
                    __floats2bfloat162_rn(acc[mi][ni][0] + b0, acc[mi][ni][1] + b1);
                *(__nv_bfloat162*)(C + (size_t)(m + 8) * N + n) =
                    __floats2bfloat162_rn(acc[mi][ni][2] + b0, acc[mi][ni][3] + b1);
            }
    } else {
        float* C = (float*)J.C;
#pragma unroll
        for (int mi = 0; mi < 4; mi++)
#pragma unroll
            for (int ni = 0; ni < 4; ni++) {
                int n = n0 + wn * 32 + ni * 8 + (lane & 3) * 2;
                if (n >= N) continue;
                int m = m0 + wm * 64 + mi * 16 + (lane >> 2);
                float b0 = bias ? bias[n] : 0.f, b1 = bias ? bias[n + 1] : 0.f;
                *(float2*)(C + (size_t)m * N + n) =
                    make_float2(acc[mi][ni][0] + b0, acc[mi][ni][1] + b1);
                *(float2*)(C + (size_t)(m + 8) * N + n) =
                    make_float2(acc[mi][ni][2] + b0, acc[mi][ni][3] + b1);
            }
    }
}

// ---------------- merged masked softmax (3 sources; fp32 + padded bf16 out) -
__global__ __launch_bounds__(128) void softmax_all(
    float* __restrict__ aq, float* __restrict__ ah, float* __restrict__ ac,
    __nv_bfloat16* __restrict__ abq, __nv_bfloat16* __restrict__ abh,
    __nv_bfloat16* __restrict__ abc,
    const int* __restrict__ txq, const int* __restrict__ txh,
    const int* __restrict__ txc)
{
    __shared__ float red[128];
    int gr = blockIdx.x;
    float* attn; const int* text; int Tk, Tkpad, r;
    __nv_bfloat16* abfb;
    if (gr < ROWS)          { attn = aq; text = txq; Tk = TK_Q; Tkpad = 64;
                              r = gr; abfb = abq; }
    else if (gr < 2 * ROWS) { attn = ah; text = txh; Tk = TK_H; Tkpad = TK_H;
                              r = gr - ROWS; abfb = abh; }
    else                    { attn = ac; text = txc; Tk = TK_C; Tkpad = TK_C;
                              r = gr - 2 * ROWS; abfb = abc; }
    const int b = r >> 7;
    float* row = attn + (long long)r * Tk;
    __nv_bfloat16* ab = abfb + (long long)r * Tkpad;
    const int* tb = text + (g_tx64 ? 2 : 1) * b * Tk;
    const int tid = threadIdx.x;
    const float scale = 0.04419417382415922f;   // 1/sqrt(512)

    float lmax = -3.4e38f;
    for (int k = tid; k < Tk; k += 128) {
        float s = row[k] * scale;
        if (get_tx(tb, k) == 0) s = -1e9f;
        row[k] = s;
        lmax = fmaxf(lmax, s);
    }
    red[tid] = lmax; __syncthreads();
    for (int s = 64; s > 0; s >>= 1) {
        if (tid < s) red[tid] = fmaxf(red[tid], red[tid + s]);
        __syncthreads();
    }
    const float mx = red[0];
    __syncthreads();
    float lsum = 0.f;
    for (int k = tid; k < Tk; k += 128) {
        float e = __expf(row[k] - mx);
        row[k] = e;
        lsum += e;
    }
    red[tid] = lsum; __syncthreads();
    for (int s = 64; s > 0; s >>= 1) {
        if (tid < s) red[tid] += red[tid + s];
        __syncthreads();
    }
    const float inv = 1.0f / red[0];
    for (int k = tid; k < Tk; k += 128) {
        float v = row[k] * inv;
        row[k] = v;
        ab[k] = __float2bfloat16(v);
    }
    for (int k = Tk + tid; k < Tkpad; k += 128)
        ab[k] = __float2bfloat16(0.f);
}

// ---------------- gates: S reduce + softmax(concat @ genW^T + genb) + C -----
__global__ __launch_bounds__(128) void gates_kernel(
    const float* __restrict__ dt, const float* __restrict__ tgt,
    const float* __restrict__ vec, const float* __restrict__ W,
    const float* __restrict__ bg, const float* __restrict__ psum,
    float* __restrict__ gates, float* __restrict__ Sout,
    float* __restrict__ Cout)
{
    __shared__ float red[4][128];
    __shared__ float sS;
    const int r = blockIdx.x, tid = threadIdx.x;

    // S = sum of this row's 250 per-tile exp sums
    float s = 0.f;
    for (int t = tid; t < NTILE; t += 128)
        s += psum[(size_t)r * NTILE + t];
    red[0][tid] = s; __syncthreads();
    for (int st = 64; st > 0; st >>= 1) {
        if (tid < st) red[0][tid] += red[0][tid + st];
        __syncthreads();
    }
    if (tid == 0) sS = red[0][0];
    __syncthreads();

    float a0 = 0, a1 = 0, a2 = 0, a3 = 0;
    for (int j = tid; j < 2560; j += 128) {
        const int part = j >> 9, d = j & 511;
        const float* src;
        switch (part) {
            case 0:  src = dt;                    break;
            case 1:  src = tgt;                   break;
            case 2:  src = vec;                   break;
            case 3:  src = vec + ROWS * DM;       break;
            default: src = vec + 2 * ROWS * DM;   break;
        }
        float x = src[(long long)r * DM + d];
        a0 = fmaf(W[j], x, a0);
        a1 = fmaf(W[2560 + j], x, a1);
        a2 = fmaf(W[5120 + j], x, a2);
        a3 = fmaf(W[7680 + j], x, a3);
    }
    red[0][tid] = a0; red[1][tid] = a1; red[2][tid] = a2; red[3][tid] = a3;
    __syncthreads();
    for (int st = 64; st > 0; st >>= 1) {
        if (tid < st) {
            red[0][tid] += red[0][tid + st]; red[1][tid] += red[1][tid + st];
            red[2][tid] += red[2][tid + st]; red[3][tid] += red[3][tid + st];
        }
        __syncthreads();
    }
    if (tid == 0) {
        float l0 = red[0][0] + bg[0], l1 = red[1][0] + bg[1];
        float l2 = red[2][0] + bg[2], l3 = red[3][0] + bg[3];
        float m = fmaxf(fmaxf(l0, l1), fmaxf(l2, l3));
        float e0 = expf(l0 - m), e1 = expf(l1 - m), e2 = expf(l2 - m), e3 = expf(l3 - m);
        float inv = 1.f / (e0 + e1 + e2 + e3);
        float g3 = e3 * inv;
        gates[r * 4 + 0] = e0 * inv; gates[r * 4 + 1] = e1 * inv;
        gates[r * 4 + 2] = e2 * inv; gates[r * 4 + 3] = g3;
        Sout[r] = sS;
        Cout[r] = logf(g3) - logf(sS);
    }
}

// ---------------- final2: scatter + single streaming output pass -------------
// Merges stream_out + fixup: per-row CTA builds the bf16 scatter buffer, then
// streams z once: untouched slots -> z + C; scattered -> log(gS*exp(z)+a).
__global__ __launch_bounds__(512) void final2_kernel(
    const float* __restrict__ z, const float* __restrict__ S_arr,
    const float* __restrict__ C_arr,
    const float* __restrict__ aq, const float* __restrict__ ah,
    const float* __restrict__ ac,
    const int* __restrict__ tq, const int* __restrict__ th,
    const int* __restrict__ tc,
    const float* __restrict__ gates, float* __restrict__ out)
{
    extern __shared__ __nv_bfloat162 addb[];   // VOC/2 pairs (64 KB)
    const int r = blockIdx.x, b = r >> 7, tid = threadIdx.x;
    const int w = g_tx64 ? 2 : 1;

    uint4* zb = (uint4*)addb;
    for (int v = tid; v < VOC * 2 / 16; v += 512) zb[v] = make_uint4(0u, 0u, 0u, 0u);
    const float g0 = gates[r * 4 + 0], g1 = gates[r * 4 + 1];
    const float g2 = gates[r * 4 + 2], g3 = gates[r * 4 + 3];
    __syncthreads();

    auto scat = [&](int idx, float v) {
        __nv_bfloat16 bv = __float2bfloat16(v);
        __nv_bfloat16 bz = __float2bfloat16(0.f);
        __nv_bfloat162 p;
        if (idx & 1) { p.x = bz; p.y = bv; } else { p.x = bv; p.y = bz; }
        atomicAdd(&addb[idx >> 1], p);
    };
    const int* tqb = tq + w * b * TK_Q;
    const int* thb = th + w * b * TK_H;
    const int* tcb = tc + w * b * TK_C;
    if (tid < TK_Q)
        scat(get_tx(tqb, tid), g0 * aq[(long long)r * TK_Q + tid]);
    for (int k = tid; k < TK_H; k += 512)
        scat(get_tx(thb, k), g1 * ah[(long long)r * TK_H + k]);
    if (tid < TK_C)
        scat(get_tx(tcb, tid), g2 * ac[(long long)r * TK_C + tid]);
    __syncthreads();

    const float S = S_arr[r];
    const float C = C_arr[r];
    const float gS = g3 / S;

    const float4* zr4 = (const float4*)(z + (long long)r * VOC);
    float4* orow = (float4*)(out + (long long)r * VOC);
    for (int i = tid; i < VOC / 4; i += 512) {
        float4 zz = __ldcs(zr4 + i);
        __nv_bfloat162 p0 = addb[i * 2], p1 = addb[i * 2 + 1];
        float a0 = __bfloat162float(p0.x), a1 = __bfloat162float(p0.y);
        float a2 = __bfloat162float(p1.x), a3 = __bfloat162float(p1.y);
        float4 o;
        o.x = (a0 == 0.f) ? zz.x + C : logf(fmaf(gS, __expf(zz.x), a0));
        o.y = (a1 == 0.f) ? zz.y + C : logf(fmaf(gS, __expf(zz.y), a1));
        o.z = (a2 == 0.f) ? zz.z + C : logf(fmaf(gS, __expf(zz.z), a2));
        o.w = (a3 == 0.f) ? zz.w + C : logf(fmaf(gS, __expf(zz.w), a3));
        __stcs(orow + i, o);
    }
}

// ---------------- launch ----------------------------------------------------
extern "C" void kernel_launch(void* const* d_in, const int* in_sizes, int n_in,
                              void* d_out, int out_size)
{
    const float* dt   = (const float*)d_in[0];
    const float* tgt  = (const float*)d_in[1];
    const float* encq = (const float*)d_in[2];
    const float* ench = (const float*)d_in[3];
    const float* encc = (const float*)d_in[4];
    const int*   txq  = (const int*)d_in[5];
    const int*   txh  = (const int*)d_in[6];
    const int*   txc  = (const int*)d_in[7];
    const float* vocab = (const float*)d_in[11];
    const float* Wqq = (const float*)d_in[12]; const float* bqq = (const float*)d_in[13];
    const float* Wkq = (const float*)d_in[14]; const float* bkq = (const float*)d_in[15];
    const float* Wqh = (const float*)d_in[16]; const float* bqh = (const float*)d_in[17];
    const float* Wkh = (const float*)d_in[18]; const float* bkh = (const float*)d_in[19];
    const float* Wqc = (const float*)d_in[20]; const float* bqc = (const float*)d_in[21];
    const float* Wkc = (const float*)d_in[22]; const float* bkc = (const float*)d_in[23];
    const float* genW = (const float*)d_in[24]; const float* genb = (const float*)d_in[25];
    float* out = (float*)d_out;

    float *zP, *psP, *SP, *CP, *aqP, *ahP, *acP, *vP, *gP;
    __nv_bfloat16 *vbP, *dbP, *eqP, *ehP, *ecP, *wbP, *qbP, *kqP, *khP, *kcP;
    __nv_bfloat16 *tqTP, *thTP, *tcTP, *abqP, *abhP, *abcP;
    cudaGetSymbolAddress((void**)&zP,  g_z);
    cudaGetSymbolAddress((void**)&psP, g_psum);
    cudaGetSymbolAddress((void**)&SP,  g_S);
    cudaGetSymbolAddress((void**)&CP,  g_C);
    cudaGetSymbolAddress((void**)&vbP, g_vocab_bf);
    cudaGetSymbolAddress((void**)&dbP, g_dt_bf);
    cudaGetSymbolAddress((void**)&eqP, g_eq_bf);
    cudaGetSymbolAddress((void**)&ehP, g_eh_bf);
    cudaGetSymbolAddress((void**)&ecP, g_ec_bf);
    cudaGetSymbolAddress((void**)&wbP, g_wbf);
    cudaGetSymbolAddress((void**)&qbP, g_qbf);
    cudaGetSymbolAddress((void**)&kqP, g_kqbf);
    cudaGetSymbolAddress((void**)&khP, g_khbf);
    cudaGetSymbolAddress((void**)&kcP, g_kcbf);
    cudaGetSymbolAddress((void**)&tqTP, g_encqT);
    cudaGetSymbolAddress((void**)&thTP, g_enchT);
    cudaGetSymbolAddress((void**)&tcTP, g_enccT);
    cudaGetSymbolAddress((void**)&abqP, g_abq);
    cudaGetSymbolAddress((void**)&abhP, g_abh);
    cudaGetSymbolAddress((void**)&abcP, g_abc);
    cudaGetSymbolAddress((void**)&aqP, g_aq);
    cudaGetSymbolAddress((void**)&ahP, g_ah);
    cudaGetSymbolAddress((void**)&acP, g_ac);
    cudaGetSymbolAddress((void**)&vP,  g_vec);
    cudaGetSymbolAddress((void**)&gP,  g_gates);

    cudaFuncSetAttribute(final2_kernel,
                         cudaFuncAttributeMaxDynamicSharedMemorySize, VOC * 2);
    cudaFuncSetAttribute(mma_nt_jobs,
                         cudaFuncAttributeMaxDynamicSharedMemorySize, MMA_SMEM);

    // Prep: probe + fp32->bf16 conversions + enc^T, one launch.
    CvtJobs cj;
    cj.src[0] = vocab; cj.dst[0] = vbP;
    cj.src[1] = dt;    cj.dst[1] = dbP;
    cj.src[2] = encq;  cj.dst[2] = eqP;
    cj.src[3] = ench;  cj.dst[3] = ehP;
    cj.src[4] = encc;  cj.dst[4] = ecP;
    cj.src[5] = Wqq;   cj.dst[5] = wbP + 0 * DM * DM;
    cj.src[6] = Wqh;   cj.dst[6] = wbP + 1 * DM * DM;
    cj.src[7] = Wqc;   cj.dst[7] = wbP + 2 * DM * DM;
    cj.src[8] = Wkq;   cj.dst[8] = wbP + 3 * DM * DM;
    cj.src[9] = Wkh;   cj.dst[9] = wbP + 4 * DM * DM;
    cj.src[10] = Wkc;  cj.dst[10] = wbP + 5 * DM * DM;
    prep_all<<<PREP_BLOCKS, 256>>>(cj, encq, ench, encc, tqTP, thTP, tcTP, txh);

    // Mega launch: 6 projections (first, critical path) + big vocab GEMM.
    {
        JobTable jt{}; int cum = 0; int i = 0;
        auto addproj = [&](const __nv_bfloat16* A, const __nv_bfloat16* B,
                           const float* bias, void* C, int M) {
            jt.j[i].A = A; jt.j[i].B = B; jt.j[i].bias = bias; jt.j[i].C = C;
            jt.j[i].psum = nullptr;
            jt.j[i].N = DM; jt.j[i].K = DM; jt.j[i].outBf = 1;
            jt.j[i].ntN = DM / 128; jt.j[i].ntM = M / 128; jt.j[i].colMajor = 0;
            cum += (M / 128) * (DM / 128);
            jt.j[i].tileEnd = cum;
            i++;
        };
        addproj(dbP, wbP + 0 * DM * DM, bqq, qbP + 0 * ROWS * DM, ROWS);
        addproj(dbP, wbP + 1 * DM * DM, bqh, qbP + 1 * ROWS * DM, ROWS);
        addproj(dbP, wbP + 2 * DM * DM, bqc, qbP + 2 * ROWS * DM, ROWS);
        addproj(eqP, wbP + 3 * DM * DM, bkq, kqP, BATCH * TK_Q);
        addproj(ehP, wbP + 4 * DM * DM, bkh, khP, BATCH * TK_H);
        addproj(ecP, wbP + 5 * DM * DM, bkc, kcP, BATCH * TK_C);
        // big vocab GEMM, column-major tile order for B L2 reuse
        jt.j[i].A = dbP; jt.j[i].B = vbP; jt.j[i].bias = nullptr; jt.j[i].C = zP;
        jt.j[i].psum = psP;
        jt.j[i].N = VOC; jt.j[i].K = DM; jt.j[i].outBf = 0;
        jt.j[i].ntN = NTILE; jt.j[i].ntM = ROWS / 128; jt.j[i].colMajor = 1;
        cum += NTILE * (ROWS / 128);
        jt.j[i].tileEnd = cum;
        i++;
        jt.njobs = i;
        mma_nt_jobs<<<cum, 256, MMA_SMEM>>>(jt);
    }

    // Scores: all 12 score GEMMs in one launch (24 tiles)
    {
        JobTable jt{}; int cum = 0, i = 0;
        auto addscore = [&](const __nv_bfloat16* A, const __nv_bfloat16* B,
                            float* C, int N) {
            jt.j[i].A = A; jt.j[i].B = B; jt.j[i].bias = nullptr; jt.j[i].C = C;
            jt.j[i].psum = nullptr;
            jt.j[i].N = N; jt.j[i].K = DM; jt.j[i].outBf = 0;
            int ntN = (N + 127) / 128;
            jt.j[i].ntN = ntN; jt.j[i].ntM = 1; jt.j[i].colMajor = 0;
            cum += ntN;
            jt.j[i].tileEnd = cum;
            i++;
        };
        for (int b = 0; b < BATCH; b++)
            addscore(qbP + 0 * ROWS * DM + b * TQ * DM, kqP + b * TK_Q * DM,
                     aqP + b * TQ * TK_Q, TK_Q);
        for (int b = 0; b < BATCH; b++)
            addscore(qbP + 1 * ROWS * DM + b * TQ * DM, khP + b * TK_H * DM,
                     ahP + b * TQ * TK_H, TK_H);
        for (int b = 0; b < BATCH; b++)
            addscore(qbP + 2 * ROWS * DM + b * TQ * DM, kcP + b * TK_C * DM,
                     acP + b * TQ * TK_C, TK_C);
        jt.njobs = 12;
        mma_nt_jobs<<<cum, 256, MMA_SMEM>>>(jt);
    }

    // Masked softmax (merged; emits fp32 + padded bf16 attn)
    softmax_all<<<3 * ROWS, 128>>>(aqP, ahP, acP, abqP, abhP, abcP,
                                   txq, txh, txc);

    // Vec: all 12 vec GEMMs on tensor cores (48 tiles): vec = attn @ enc
    {
        JobTable jt{}; int cum = 0, i = 0;
        auto addvec = [&](const __nv_bfloat16* A, const __nv_bfloat16* B,
                          float* C, int K) {
            jt.j[i].A = A; jt.j[i].B = B; jt.j[i].bias = nullptr; jt.j[i].C = C;
            jt.j[i].psum = nullptr;
            jt.j[i].N = DM; jt.j[i].K = K; jt.j[i].outBf = 0;
            jt.j[i].ntN = DM / 128; jt.j[i].ntM = 1; jt.j[i].colMajor = 0;
            cum += DM / 128;
            jt.j[i].tileEnd = cum;
            i++;
        };
        for (int b = 0; b < BATCH; b++)
            addvec(abqP + b * TQ * 64, tqTP + b * DM * 64,
                   vP + 0 * ROWS * DM + b * TQ * DM, 64);
        for (int b = 0; b < BATCH; b++)
            addvec(abhP + b * TQ * TK_H, thTP + b * DM * TK_H,
                   vP + 1 * ROWS * DM + b * TQ * DM, TK_H);
        for (int b = 0; b < BATCH; b++)
            addvec(abcP + b * TQ * TK_C, tcTP + b * DM * TK_C,
                   vP + 2 * ROWS * DM + b * TQ * DM, TK_C);
        jt.njobs = 12;
        mma_nt_jobs<<<cum, 256, MMA_SMEM>>>(jt);
    }

    // Gates (+ S reduction + C = log g3 - log S)
    gates_kernel<<<ROWS, 128>>>(dt, tgt, vP, genW, genb, psP, gP, SP, CP);

    // Final: scatter + single streaming pass (merged stream_out + fixup)
    final2_kernel<<<ROWS, 512, VOC * 2>>>(zP, SP, CP, aqP, ahP, acP,
                                          txq, txh, txc, gP, out);
}